// round 12
// baseline (speedup 1.0000x reference)
#include <cuda_runtime.h>
#include <cuda_bf16.h>
#include <math.h>

#define Bb   4
#define Ss   1024
#define EMB  128
#define Hh   4
#define Dd   32
#define Tt   (Ss-1)          // 1023
#define NROW (Bb*Ss)         // 4096
#define NSPL 3               // i-dimension split factor for kC
#define SCALE 0.17677669529663687f   // 1/sqrt(32)
#define L2E   1.4426950408889634f
#define SCALE2 (SCALE*L2E)           // folds exp->exp2 conversion

typedef unsigned long long u64;

// ---------------- scratch (static device allocations only) ----------------
__device__ float g_e   [NROW*EMB];
__device__ float g_Q   [NROW*EMB];
__device__ float g_K   [NROW*EMB];
__device__ float g_V   [NROW*EMB];
__device__ float g_sr  [NROW*Hh];
__device__ float g_EpEx[NROW*Hh];   // exclusive cumsum of ex, per (b,s,h)
__device__ float g_PpEx[NROW];      // exclusive cumsum of g, per (b,s)
__device__ float g_theta[Hh];
__device__ float g_pacc [NSPL*NROW*EMB];   // unnormalized partial ctx
__device__ float g_plsum[NSPL*NROW*Hh];    // partial softmax denominators

// ---------------- f32x2 helpers (sm_103a packed fp32) ----------------
__device__ __forceinline__ u64 pk2(float lo, float hi)
{
    u64 r; asm("mov.b64 %0, {%1, %2};" : "=l"(r) : "f"(lo), "f"(hi)); return r;
}
__device__ __forceinline__ u64 ffma2(u64 a, u64 b, u64 c)
{
    u64 d; asm("fma.rn.f32x2 %0, %1, %2, %3;" : "=l"(d) : "l"(a), "l"(b), "l"(c));
    return d;
}

// ---------------- fast exp2: no MUFU, pure FMA/ALU ----------------
__device__ __forceinline__ float fexp2f(float y)
{
    y = fmaxf(y, -125.0f);                       // clamp: avoids exponent underflow garbage
    float z = y + 12582912.0f;                   // 1.5*2^23: round-to-nearest-int trick
    int   j = __float_as_int(z) - 0x4B400000;    // integer part
    float f = y - (z - 12582912.0f);             // fractional part in [-0.5, 0.5]
    float r = fmaf(f, 0.0013333558f, 0.0096181291f);
    r = fmaf(f, r, 0.0555041087f);
    r = fmaf(f, r, 0.2402265069f);
    r = fmaf(f, r, 0.6931471806f);
    r = fmaf(f, r, 1.0f);
    return __int_as_float(__float_as_int(r) + (j << 23));   // * 2^j
}

// ---------------- shared-mem GEMM helper: 16 rows x 128 cols ----------------
template<int KG>   // KG = K/4
__device__ __forceinline__ void gemmT(const float* Esh, const float* __restrict__ W,
                                      int c, float acc[16])
{
    const float4* e4 = reinterpret_cast<const float4*>(Esh);
    #pragma unroll 4
    for (int k4 = 0; k4 < KG; k4++) {
        const float* wp = W + (k4*4)*128 + c;
        float w0 = wp[0], w1 = wp[128], w2 = wp[256], w3 = wp[384];
        #pragma unroll
        for (int r = 0; r < 16; r++) {
            float4 ev = e4[r*KG + k4];
            acc[r] = fmaf(ev.x, w0, acc[r]);
            acc[r] = fmaf(ev.y, w1, acc[r]);
            acc[r] = fmaf(ev.z, w2, acc[r]);
            acc[r] = fmaf(ev.w, w3, acc[r]);
        }
    }
}

// ---------------- kernel A: gather + ansc + Q/K/inter/V + sr ----------------
__global__ __launch_bounds__(128) void kA(
    const int* __restrict__ idx, const int* __restrict__ flg,
    const float* __restrict__ item_emb, const float* __restrict__ ans_emb,
    const float* __restrict__ Wq, const float* __restrict__ bq,
    const float* __restrict__ Wk, const float* __restrict__ bk,
    const float* __restrict__ Wv, const float* __restrict__ bv,
    const float* __restrict__ Wh, const float* __restrict__ bh)
{
    __shared__ __align__(16) float e_sh[16*128];
    __shared__ __align__(16) float q_sh[16*128];
    __shared__ __align__(16) float k_sh[16*128];
    __shared__ __align__(16) float i_sh[16*128];
    __shared__ int fl[16];

    int tid  = threadIdx.x;           // = output column c
    int row0 = blockIdx.x * 16;

    #pragma unroll
    for (int r = 0; r < 16; r++) {
        int row = row0 + r;
        float v = item_emb[(long)idx[row]*128 + tid];
        e_sh[r*128 + tid] = v;
        g_e[row*128 + tid] = v;
    }
    if (tid < 16) fl[tid] = flg[row0 + tid];

    // inline ansc: per-thread column of (ans_emb @ Wh_bot + bh), both flags
    float a0 = bh[tid], a1 = a0;
    #pragma unroll 4
    for (int k = 0; k < 128; k++) {
        float wv = Wh[(128 + k)*128 + tid];
        a0 = fmaf(ans_emb[k],       wv, a0);
        a1 = fmaf(ans_emb[128 + k], wv, a1);
    }
    __syncthreads();

    float acc[16];

    // Q
    #pragma unroll
    for (int r = 0; r < 16; r++) acc[r] = 0.f;
    gemmT<32>(e_sh, Wq, tid, acc);
    {
        float bb = bq[tid];
        #pragma unroll
        for (int r = 0; r < 16; r++) {
            float v = acc[r] + bb;
            q_sh[r*128 + tid] = v;
            g_Q[(row0 + r)*128 + tid] = v;
        }
    }
    // K
    #pragma unroll
    for (int r = 0; r < 16; r++) acc[r] = 0.f;
    gemmT<32>(e_sh, Wk, tid, acc);
    {
        float bb = bk[tid];
        #pragma unroll
        for (int r = 0; r < 16; r++) {
            float v = acc[r] + bb;
            k_sh[r*128 + tid] = v;
            g_K[(row0 + r)*128 + tid] = v;
        }
    }
    // inter = e @ Wh_top + ansc[flag]
    #pragma unroll
    for (int r = 0; r < 16; r++) acc[r] = 0.f;
    gemmT<32>(e_sh, Wh, tid, acc);
    #pragma unroll
    for (int r = 0; r < 16; r++)
        i_sh[r*128 + tid] = acc[r] + (fl[r] ? a1 : a0);
    __syncthreads();

    // V = inter @ Wv + bv
    #pragma unroll
    for (int r = 0; r < 16; r++) acc[r] = 0.f;
    gemmT<32>(i_sh, Wv, tid, acc);
    {
        float bb = bv[tid];
        #pragma unroll
        for (int r = 0; r < 16; r++)
            g_V[(row0 + r)*128 + tid] = acc[r] + bb;
    }

    // sr[row][h] = dot(Q_h, K_h) * scale
    if (tid < 64) {
        int r = tid >> 2, h = tid & 3;
        float s = 0.f;
        #pragma unroll
        for (int d = 0; d < 32; d++)
            s = fmaf(q_sh[r*128 + h*32 + d], k_sh[r*128 + h*32 + d], s);
        g_sr[(row0 + r)*Hh + h] = s * SCALE;
    }
}

// ---------------- kernel B: parallel scans, one per block (+ theta) --------
__device__ __forceinline__ float blockScanExcl(float x, int lane, int w, float* wt)
{
    float v = x;
    #pragma unroll
    for (int off = 1; off < 32; off <<= 1) {
        float t = __shfl_up_sync(0xffffffffu, v, off);
        if (lane >= off) v += t;
    }
    if (lane == 31) wt[w] = v;
    __syncthreads();
    if (w == 0) {
        float tv = wt[lane];
        #pragma unroll
        for (int off = 1; off < 32; off <<= 1) {
            float t = __shfl_up_sync(0xffffffffu, tv, off);
            if (lane >= off) tv += t;
        }
        wt[lane] = tv;
    }
    __syncthreads();
    float pre = (w > 0) ? wt[w - 1] : 0.f;
    return pre + v - x;     // exclusive prefix
}

__global__ __launch_bounds__(1024) void kB(const float* __restrict__ gaps,
                                           const float* __restrict__ traw)
{
    __shared__ float wt[32];
    int q = blockIdx.x;          // 0 = Pp; 1..4 = head q-1
    int b = blockIdx.y;
    int s = threadIdx.x;
    int lane = s & 31, w = s >> 5;

    if (q == 0 && s < Hh) {
        float x = traw[s];
        g_theta[s] = log1pf(expf(x)) + 1e-4f;   // softplus + eps (redundant per b, benign)
    }

    float x;
    if (q == 0) x = fmaxf(gaps[b*Ss + s], 1.0f);
    else        x = __expf(g_sr[(b*Ss + s)*Hh + (q - 1)]);
    // exp without max-subtraction: rel = (Et-Ei)/Et is invariant to the shift
    float ex = blockScanExcl(x, lane, w, wt);
    if (q == 0) g_PpEx[b*Ss + s] = ex;
    else        g_EpEx[(b*Ss + s)*Hh + (q - 1)] = ex;
}

// ---------------- kernel C: GEMM-tiled decayed attention, split-K over i ----
// Grid (8, NSPL, 16). 384 blocks, 3 co-resident per SM -> one full wave.
// GEMM1 uses packed fma.rn.f32x2 (accumulators packed over t-pairs).
#define PADQ 68
#define PADP 68
__global__ __launch_bounds__(256) void kC()
{
    __shared__ __align__(16) float QsT[32*PADQ];
    __shared__ __align__(16) float KsT[32*PADQ];
    __shared__ __align__(16) float Vs [64*32];
    __shared__ __align__(16) float Ps [64*PADP];
    __shared__ float Pts[64], Ets[64], iEts[64];
    __shared__ float Pis[64], Eis[64];
    __shared__ float Ls[64];

    int bh = blockIdx.z;
    int b  = bh >> 2, h = bh & 3;
    int r  = blockIdx.y;                 // split index
    int pr = blockIdx.x;                 // 0..7
    int tid = threadIdx.x;
    int tx = tid & 15, ty = tid >> 4;    // epilogue/GEMM1 mapping
    int lane = tid & 31, w = tid >> 5;   // GEMM2 mapping

    float th2 = g_theta[h] * L2E;        // folds exp -> exp2

    #pragma unroll 1
    for (int ph = 0; ph < 2; ph++) {
        int jt = ph ? (15 - pr) : pr;
        int t0 = 1 + jt*64;

        // stage Q tile (transposed) + per-t stats
        for (int e = tid; e < 2048; e += 256) {
            int tl = e >> 5, d = e & 31;
            int t = min(t0 + tl, Ss - 1);
            QsT[d*PADQ + tl] = g_Q[(b*Ss + t)*128 + h*32 + d];
        }
        if (tid < 64) {
            int t = min(t0 + tid, Ss - 1);
            Pts[tid] = g_PpEx[b*Ss + t];
            float Et = g_EpEx[(b*Ss + t)*Hh + h];
            Ets[tid]  = Et;
            iEts[tid] = 1.0f / Et;
        }

        float lsum[4] = {0.f, 0.f, 0.f, 0.f};
        float acc[8]  = {0.f,0.f,0.f,0.f,0.f,0.f,0.f,0.f};

        int ntile = jt + 1;
        for (int it = r; it < ntile; it += NSPL) {
            int i0 = it*64;
            __syncthreads();   // prev GEMM2 done before overwriting K/V/Ps
            // stage K (transposed), V (row-major), per-i stats
            for (int e = tid; e < 2048; e += 256) {
                int il = e >> 5, d = e & 31;
                int gi = (b*Ss + i0 + il)*128 + h*32 + d;
                KsT[d*PADQ + il] = g_K[gi];
                Vs[il*32 + d]    = g_V[gi];
            }
            if (tid < 64) {
                Pis[tid] = g_PpEx[b*Ss + i0 + tid];
                Eis[tid] = g_EpEx[(b*Ss + i0 + tid)*Hh + h];
            }
            __syncthreads();

            // ---- GEMM1 (f32x2): s packed over t-pairs ----
            u64 s01[4] = {0,0,0,0}, s23[4] = {0,0,0,0};
            #pragma unroll
            for (int d = 0; d < 32; d++) {
                float4 a  = *reinterpret_cast<const float4*>(&QsT[d*PADQ + ty*4]);
                float4 k4 = *reinterpret_cast<const float4*>(&KsT[d*PADQ + tx*4]);
                u64 a01 = pk2(a.x, a.y), a23 = pk2(a.z, a.w);
                u64 kd0 = pk2(k4.x, k4.x), kd1 = pk2(k4.y, k4.y);
                u64 kd2 = pk2(k4.z, k4.z), kd3 = pk2(k4.w, k4.w);
                s01[0] = ffma2(a01, kd0, s01[0]);  s23[0] = ffma2(a23, kd0, s23[0]);
                s01[1] = ffma2(a01, kd1, s01[1]);  s23[1] = ffma2(a23, kd1, s23[1]);
                s01[2] = ffma2(a01, kd2, s01[2]);  s23[2] = ffma2(a23, kd2, s23[2]);
                s01[3] = ffma2(a01, kd3, s01[3]);  s23[3] = ffma2(a23, kd3, s23[3]);
            }
            float sm[4][4];
            #pragma unroll
            for (int ii = 0; ii < 4; ii++) {
                asm("mov.b64 {%0, %1}, %2;" : "=f"(sm[0][ii]), "=f"(sm[1][ii]) : "l"(s01[ii]));
                asm("mov.b64 {%0, %1}, %2;" : "=f"(sm[2][ii]), "=f"(sm[3][ii]) : "l"(s23[ii]));
            }

            // ---- epilogue: decay + exp (fexp2f), store p ----
            float4 Pi4 = *reinterpret_cast<const float4*>(&Pis[tx*4]);
            float4 Ei4 = *reinterpret_cast<const float4*>(&Eis[tx*4]);
            float piv[4] = {Pi4.x, Pi4.y, Pi4.z, Pi4.w};
            float eiv[4] = {Ei4.x, Ei4.y, Ei4.z, Ei4.w};
            #pragma unroll
            for (int ti = 0; ti < 4; ti++) {
                int tl = ty*4 + ti;
                int t  = t0 + tl;
                float Pt = Pts[tl], Et = Ets[tl], iE = iEts[tl];
                float4 pv;
                float pout[4];
                #pragma unroll
                for (int ii = 0; ii < 4; ii++) {
                    int i = i0 + tx*4 + ii;
                    float p = 0.f;
                    if (i < t && t < Ss) {
                        float step = (float)(t - i);
                        float gd   = Pt - piv[ii];
                        float relv = (Et - eiv[ii]) * iE;
                        float pd   = step * gd * relv;
                        float decay = fexp2f(-th2 * pd);           // = exp(-theta*pd)
                        p = fexp2f((sm[ti][ii] * SCALE2) * decay); // = exp(raw*decay)
                    }
                    lsum[ti] += p;
                    pout[ii] = p;
                }
                pv.x = pout[0]; pv.y = pout[1]; pv.z = pout[2]; pv.w = pout[3];
                *reinterpret_cast<float4*>(&Ps[tl*PADP + tx*4]) = pv;
            }
            __syncthreads();

            // ---- GEMM2: ctx[t][d] += sum_i p[t][i] * V[i][d] ----
            #pragma unroll 4
            for (int i4 = 0; i4 < 16; i4++) {
                float v0 = Vs[(i4*4+0)*32 + lane];
                float v1 = Vs[(i4*4+1)*32 + lane];
                float v2 = Vs[(i4*4+2)*32 + lane];
                float v3 = Vs[(i4*4+3)*32 + lane];
                #pragma unroll
                for (int tt = 0; tt < 8; tt++) {
                    float4 p4 = *reinterpret_cast<const float4*>(&Ps[(w*8+tt)*PADP + i4*4]);
                    float a = acc[tt];
                    a = fmaf(p4.x, v0, a);
                    a = fmaf(p4.y, v1, a);
                    a = fmaf(p4.z, v2, a);
                    a = fmaf(p4.w, v3, a);
                    acc[tt] = a;
                }
            }
        }

        // reduce partial lsum across tx (within half-warp)
        #pragma unroll
        for (int off = 1; off < 16; off <<= 1) {
            #pragma unroll
            for (int ti = 0; ti < 4; ti++)
                lsum[ti] += __shfl_xor_sync(0xffffffffu, lsum[ti], off);
        }
        if (tx == 0) {
            #pragma unroll
            for (int ti = 0; ti < 4; ti++)
                Ls[ty*4 + ti] = lsum[ti];
        }
        __syncthreads();

        // write unnormalized partials (warp w owns t-rows w*8..w*8+7, lane = d)
        #pragma unroll
        for (int tt = 0; tt < 8; tt++) {
            int tl = w*8 + tt;
            int t  = t0 + tl;
            if (t < Ss) {
                g_pacc[r*(NROW*EMB) + (b*Ss + t)*128 + h*32 + lane] = acc[tt];
                if (lane == 0)
                    g_plsum[r*(NROW*Hh) + (b*Ss + t)*Hh + h] = Ls[tl];
            }
        }
        __syncthreads();   // before next phase restages
    }
}

// ---------------- kernel D: combine + final MLP + sigmoid + valid mask -----
__global__ __launch_bounds__(128) void kD(
    const float* __restrict__ W1, const float* __restrict__ b1,
    const float* __restrict__ W2, const float* __restrict__ b2,
    float* __restrict__ out, int npred, int out_size)
{
    __shared__ __align__(16) float f_sh[16*256];
    __shared__ float h_sh[16*128];
    __shared__ float w2s[128];

    int tid  = threadIdx.x;
    int row0 = blockIdx.x * 16;
    w2s[tid] = W2[tid];

    // valid mask: out[Bb*Tt + row] = 1.0f
    if (tid < 16) {
        int vrow = row0 + tid;
        if (vrow < Bb*Tt && Bb*Tt + vrow < out_size)
            out[Bb*Tt + vrow] = 1.0f;
    }

    int nrows = min(16, Bb*Tt - row0);
    for (int r = 0; r < nrows; r++) {
        int row = row0 + r;
        int bb  = row / Tt;
        int tt  = row % Tt;
        int t   = tt + 1;
        int base = (bb*Ss + t)*128 + tid;
        int lidx = (bb*Ss + t)*Hh + (tid >> 5);
        float a = g_pacc[base] + g_pacc[NROW*EMB + base] + g_pacc[2*(NROW*EMB) + base];
        float l = g_plsum[lidx] + g_plsum[NROW*Hh + lidx] + g_plsum[2*(NROW*Hh) + lidx];
        f_sh[r*256 + tid]       = a / l;
        f_sh[r*256 + 128 + tid] = g_e[base];
    }
    for (int r = nrows; r < 16; r++) {
        f_sh[r*256 + tid] = 0.f; f_sh[r*256 + 128 + tid] = 0.f;
    }
    __syncthreads();

    float acc[16];
    #pragma unroll
    for (int r = 0; r < 16; r++) acc[r] = 0.f;
    gemmT<64>(f_sh, W1, tid, acc);
    {
        float bb = b1[tid];
        #pragma unroll
        for (int r = 0; r < 16; r++)
            h_sh[r*128 + tid] = fmaxf(acc[r] + bb, 0.f);
    }
    __syncthreads();

    int lane = tid & 31, wp = tid >> 5;
    for (int r = wp; r < nrows; r += 4) {
        float s = 0.f;
        #pragma unroll
        for (int c = lane; c < 128; c += 32)
            s = fmaf(h_sh[r*128 + c], w2s[c], s);
        #pragma unroll
        for (int off = 16; off; off >>= 1)
            s += __shfl_xor_sync(0xffffffffu, s, off);
        if (lane == 0) {
            int row = row0 + r;
            if (row < npred) {
                float logit = s + b2[0];
                out[row] = 1.0f / (1.0f + __expf(-logit));
            }
        }
    }
}

__global__ void kFill(float* out, int start, int n)
{
    int i = blockIdx.x*blockDim.x + threadIdx.x;
    if (i < n) out[start + i] = 1.0f;
}

// ---------------- launch ----------------
extern "C" void kernel_launch(void* const* d_in, const int* in_sizes, int n_in,
                              void* d_out, int out_size)
{
    const int*   idx      = (const int*)  d_in[0];
    const int*   flg      = (const int*)  d_in[1];
    const float* gaps     = (const float*)d_in[2];
    const float* item_emb = (const float*)d_in[3];
    const float* ans_emb  = (const float*)d_in[4];
    const float* Wq = (const float*)d_in[5];  const float* bq = (const float*)d_in[6];
    const float* Wk = (const float*)d_in[7];  const float* bk = (const float*)d_in[8];
    const float* Wv = (const float*)d_in[9];  const float* bv = (const float*)d_in[10];
    const float* Wh = (const float*)d_in[11]; const float* bh = (const float*)d_in[12];
    const float* W1 = (const float*)d_in[13]; const float* b1 = (const float*)d_in[14];
    const float* W2 = (const float*)d_in[15]; const float* b2 = (const float*)d_in[16];
    const float* th = (const float*)d_in[17];
    float* out = (float*)d_out;

    kA<<<NROW/16, 128>>>(idx, flg, item_emb, ans_emb, Wq, bq, Wk, bk, Wv, bv, Wh, bh);
    dim3 gB(5, Bb);
    kB<<<gB, 1024>>>(gaps, th);
    dim3 gC(8, NSPL, Bb*Hh);
    kC<<<gC, 256>>>();
    int npred = (out_size < Bb*Tt) ? out_size : Bb*Tt;
    kD<<<(Bb*Tt + 15)/16, 128>>>(W1, b1, W2, b2, out, npred, out_size);
    int extra = out_size - 2*Bb*Tt;
    if (extra > 0)
        kFill<<<(extra + 255)/256, 256>>>(out, 2*Bb*Tt, extra);
}

// round 14
// speedup vs baseline: 1.0646x; 1.0646x over previous
#include <cuda_runtime.h>
#include <cuda_bf16.h>
#include <math.h>

#define Bb   4
#define Ss   1024
#define EMB  128
#define Hh   4
#define Dd   32
#define Tt   (Ss-1)          // 1023
#define NROW (Bb*Ss)         // 4096
#define NSPL 3               // i-dimension split factor for kC
#define SCALE 0.17677669529663687f   // 1/sqrt(32)
#define L2E   1.4426950408889634f
#define SCALE2 (SCALE*L2E)           // folds exp->exp2 conversion

typedef unsigned long long u64;

// ---------------- scratch (static device allocations only) ----------------
__device__ float g_e   [NROW*EMB];
__device__ float g_Q   [NROW*EMB];
__device__ float g_K   [NROW*EMB];
__device__ float g_V   [NROW*EMB];
__device__ float g_sr  [NROW*Hh];
__device__ float g_EpEx[NROW*Hh];   // exclusive cumsum of ex, per (b,s,h)
__device__ float g_PpEx[NROW];      // exclusive cumsum of g, per (b,s)
__device__ float g_theta[Hh];
__device__ float g_pacc [NSPL*NROW*EMB];   // unnormalized partial ctx
__device__ float g_plsum[NSPL*NROW*Hh];    // partial softmax denominators

// ---------------- f32x2 helpers (sm_103a packed fp32) ----------------
__device__ __forceinline__ u64 pk2(float lo, float hi)
{
    u64 r; asm("mov.b64 %0, {%1, %2};" : "=l"(r) : "f"(lo), "f"(hi)); return r;
}
__device__ __forceinline__ u64 ffma2(u64 a, u64 b, u64 c)
{
    u64 d; asm("fma.rn.f32x2 %0, %1, %2, %3;" : "=l"(d) : "l"(a), "l"(b), "l"(c));
    return d;
}

// ---------------- fast exp2: no MUFU, pure FMA/ALU ----------------
__device__ __forceinline__ float fexp2f(float y)
{
    y = fmaxf(y, -125.0f);                       // clamp: avoids exponent underflow garbage
    float z = y + 12582912.0f;                   // 1.5*2^23: round-to-nearest-int trick
    int   j = __float_as_int(z) - 0x4B400000;    // integer part
    float f = y - (z - 12582912.0f);             // fractional part in [-0.5, 0.5]
    float r = fmaf(f, 0.0013333558f, 0.0096181291f);
    r = fmaf(f, r, 0.0555041087f);
    r = fmaf(f, r, 0.2402265069f);
    r = fmaf(f, r, 0.6931471806f);
    r = fmaf(f, r, 1.0f);
    return __int_as_float(__float_as_int(r) + (j << 23));   // * 2^j
}

// ---------------- shared-mem GEMM helper: 16 rows x 128 cols ----------------
template<int KG>   // KG = K/4
__device__ __forceinline__ void gemmT(const float* Esh, const float* __restrict__ W,
                                      int c, float acc[16])
{
    const float4* e4 = reinterpret_cast<const float4*>(Esh);
    #pragma unroll 4
    for (int k4 = 0; k4 < KG; k4++) {
        const float* wp = W + (k4*4)*128 + c;
        float w0 = wp[0], w1 = wp[128], w2 = wp[256], w3 = wp[384];
        #pragma unroll
        for (int r = 0; r < 16; r++) {
            float4 ev = e4[r*KG + k4];
            acc[r] = fmaf(ev.x, w0, acc[r]);
            acc[r] = fmaf(ev.y, w1, acc[r]);
            acc[r] = fmaf(ev.z, w2, acc[r]);
            acc[r] = fmaf(ev.w, w3, acc[r]);
        }
    }
}

// ---------------- kernel A: gather + ansc + Q/K/inter/V + sr ----------------
__global__ __launch_bounds__(128) void kA(
    const int* __restrict__ idx, const int* __restrict__ flg,
    const float* __restrict__ item_emb, const float* __restrict__ ans_emb,
    const float* __restrict__ Wq, const float* __restrict__ bq,
    const float* __restrict__ Wk, const float* __restrict__ bk,
    const float* __restrict__ Wv, const float* __restrict__ bv,
    const float* __restrict__ Wh, const float* __restrict__ bh)
{
    __shared__ __align__(16) float e_sh[16*128];
    __shared__ __align__(16) float q_sh[16*128];
    __shared__ __align__(16) float k_sh[16*128];
    __shared__ __align__(16) float i_sh[16*128];
    __shared__ int fl[16];

    int tid  = threadIdx.x;           // = output column c
    int row0 = blockIdx.x * 16;

    #pragma unroll
    for (int r = 0; r < 16; r++) {
        int row = row0 + r;
        float v = item_emb[(long)idx[row]*128 + tid];
        e_sh[r*128 + tid] = v;
        g_e[row*128 + tid] = v;
    }
    if (tid < 16) fl[tid] = flg[row0 + tid];

    // inline ansc: per-thread column of (ans_emb @ Wh_bot + bh), both flags
    float a0 = bh[tid], a1 = a0;
    #pragma unroll 4
    for (int k = 0; k < 128; k++) {
        float wv = Wh[(128 + k)*128 + tid];
        a0 = fmaf(ans_emb[k],       wv, a0);
        a1 = fmaf(ans_emb[128 + k], wv, a1);
    }
    __syncthreads();

    float acc[16];

    // Q
    #pragma unroll
    for (int r = 0; r < 16; r++) acc[r] = 0.f;
    gemmT<32>(e_sh, Wq, tid, acc);
    {
        float bb = bq[tid];
        #pragma unroll
        for (int r = 0; r < 16; r++) {
            float v = acc[r] + bb;
            q_sh[r*128 + tid] = v;
            g_Q[(row0 + r)*128 + tid] = v;
        }
    }
    // K
    #pragma unroll
    for (int r = 0; r < 16; r++) acc[r] = 0.f;
    gemmT<32>(e_sh, Wk, tid, acc);
    {
        float bb = bk[tid];
        #pragma unroll
        for (int r = 0; r < 16; r++) {
            float v = acc[r] + bb;
            k_sh[r*128 + tid] = v;
            g_K[(row0 + r)*128 + tid] = v;
        }
    }
    // inter = e @ Wh_top + ansc[flag]
    #pragma unroll
    for (int r = 0; r < 16; r++) acc[r] = 0.f;
    gemmT<32>(e_sh, Wh, tid, acc);
    #pragma unroll
    for (int r = 0; r < 16; r++)
        i_sh[r*128 + tid] = acc[r] + (fl[r] ? a1 : a0);
    __syncthreads();

    // V = inter @ Wv + bv
    #pragma unroll
    for (int r = 0; r < 16; r++) acc[r] = 0.f;
    gemmT<32>(i_sh, Wv, tid, acc);
    {
        float bb = bv[tid];
        #pragma unroll
        for (int r = 0; r < 16; r++)
            g_V[(row0 + r)*128 + tid] = acc[r] + bb;
    }

    // sr[row][h] = dot(Q_h, K_h) * scale
    if (tid < 64) {
        int r = tid >> 2, h = tid & 3;
        float s = 0.f;
        #pragma unroll
        for (int d = 0; d < 32; d++)
            s = fmaf(q_sh[r*128 + h*32 + d], k_sh[r*128 + h*32 + d], s);
        g_sr[(row0 + r)*Hh + h] = s * SCALE;
    }
}

// ---------------- kernel B: parallel scans, one per block (+ theta) --------
__device__ __forceinline__ float blockScanExcl(float x, int lane, int w, float* wt)
{
    float v = x;
    #pragma unroll
    for (int off = 1; off < 32; off <<= 1) {
        float t = __shfl_up_sync(0xffffffffu, v, off);
        if (lane >= off) v += t;
    }
    if (lane == 31) wt[w] = v;
    __syncthreads();
    if (w == 0) {
        float tv = wt[lane];
        #pragma unroll
        for (int off = 1; off < 32; off <<= 1) {
            float t = __shfl_up_sync(0xffffffffu, tv, off);
            if (lane >= off) tv += t;
        }
        wt[lane] = tv;
    }
    __syncthreads();
    float pre = (w > 0) ? wt[w - 1] : 0.f;
    return pre + v - x;     // exclusive prefix
}

__global__ __launch_bounds__(1024) void kB(const float* __restrict__ gaps,
                                           const float* __restrict__ traw)
{
    __shared__ float wt[32];
    int q = blockIdx.x;          // 0 = Pp; 1..4 = head q-1
    int b = blockIdx.y;
    int s = threadIdx.x;
    int lane = s & 31, w = s >> 5;

    if (q == 0 && s < Hh) {
        float x = traw[s];
        g_theta[s] = log1pf(expf(x)) + 1e-4f;   // softplus + eps (redundant per b, benign)
    }

    float x;
    if (q == 0) x = fmaxf(gaps[b*Ss + s], 1.0f);
    else        x = __expf(g_sr[(b*Ss + s)*Hh + (q - 1)]);
    // exp without max-subtraction: rel = (Et-Ei)/Et is invariant to the shift
    float ex = blockScanExcl(x, lane, w, wt);
    if (q == 0) g_PpEx[b*Ss + s] = ex;
    else        g_EpEx[(b*Ss + s)*Hh + (q - 1)] = ex;
}

// ---------------- kernel C: GEMM-tiled decayed attention, split-K over i ----
// Grid (8, NSPL, 16). 384 blocks, 3 co-resident per SM -> one full wave.
#define PADQ 68
#define PADP 68
__global__ __launch_bounds__(256) void kC()
{
    __shared__ __align__(16) float QsT[32*PADQ];
    __shared__ __align__(16) float KsT[32*PADQ];
    __shared__ __align__(16) float Vs [64*32];
    __shared__ __align__(16) float Ps [64*PADP];
    __shared__ float Pts[64], Ets[64], iEts[64];
    __shared__ float Pis[64], Eis[64];
    __shared__ float Ls[64];

    int bh = blockIdx.z;
    int b  = bh >> 2, h = bh & 3;
    int r  = blockIdx.y;                 // split index
    int pr = blockIdx.x;                 // 0..7
    int tid = threadIdx.x;
    int tx = tid & 15, ty = tid >> 4;    // epilogue/GEMM1 mapping
    int lane = tid & 31, w = tid >> 5;   // GEMM2 mapping

    float th2 = g_theta[h] * L2E;        // folds exp -> exp2

    #pragma unroll 1
    for (int ph = 0; ph < 2; ph++) {
        int jt = ph ? (15 - pr) : pr;
        int t0 = 1 + jt*64;

        // stage Q tile (transposed) + per-t stats
        for (int e = tid; e < 2048; e += 256) {
            int tl = e >> 5, d = e & 31;
            int t = min(t0 + tl, Ss - 1);
            QsT[d*PADQ + tl] = g_Q[(b*Ss + t)*128 + h*32 + d];
        }
        if (tid < 64) {
            int t = min(t0 + tid, Ss - 1);
            Pts[tid] = g_PpEx[b*Ss + t];
            float Et = g_EpEx[(b*Ss + t)*Hh + h];
            Ets[tid]  = Et;
            iEts[tid] = 1.0f / Et;
        }

        float lsum[4] = {0.f, 0.f, 0.f, 0.f};
        float acc[8]  = {0.f,0.f,0.f,0.f,0.f,0.f,0.f,0.f};

        int ntile = jt + 1;
        for (int it = r; it < ntile; it += NSPL) {
            int i0 = it*64;
            __syncthreads();   // prev GEMM2 done before overwriting K/V/Ps
            // stage K (transposed), V (row-major), per-i stats
            for (int e = tid; e < 2048; e += 256) {
                int il = e >> 5, d = e & 31;
                int gi = (b*Ss + i0 + il)*128 + h*32 + d;
                KsT[d*PADQ + il] = g_K[gi];
                Vs[il*32 + d]    = g_V[gi];
            }
            if (tid < 64) {
                Pis[tid] = g_PpEx[b*Ss + i0 + tid];
                Eis[tid] = g_EpEx[(b*Ss + i0 + tid)*Hh + h];
            }
            __syncthreads();

            // ---- GEMM1 (f32x2): s packed over t-pairs ----
            u64 s01[4] = {0,0,0,0}, s23[4] = {0,0,0,0};
            #pragma unroll
            for (int d = 0; d < 32; d++) {
                float4 a  = *reinterpret_cast<const float4*>(&QsT[d*PADQ + ty*4]);
                float4 k4 = *reinterpret_cast<const float4*>(&KsT[d*PADQ + tx*4]);
                u64 a01 = pk2(a.x, a.y), a23 = pk2(a.z, a.w);
                u64 kd0 = pk2(k4.x, k4.x), kd1 = pk2(k4.y, k4.y);
                u64 kd2 = pk2(k4.z, k4.z), kd3 = pk2(k4.w, k4.w);
                s01[0] = ffma2(a01, kd0, s01[0]);  s23[0] = ffma2(a23, kd0, s23[0]);
                s01[1] = ffma2(a01, kd1, s01[1]);  s23[1] = ffma2(a23, kd1, s23[1]);
                s01[2] = ffma2(a01, kd2, s01[2]);  s23[2] = ffma2(a23, kd2, s23[2]);
                s01[3] = ffma2(a01, kd3, s01[3]);  s23[3] = ffma2(a23, kd3, s23[3]);
            }
            float sm[4][4];
            #pragma unroll
            for (int ii = 0; ii < 4; ii++) {
                asm("mov.b64 {%0, %1}, %2;" : "=f"(sm[0][ii]), "=f"(sm[1][ii]) : "l"(s01[ii]));
                asm("mov.b64 {%0, %1}, %2;" : "=f"(sm[2][ii]), "=f"(sm[3][ii]) : "l"(s23[ii]));
            }

            // ---- epilogue: decay + exp (fexp2f), store p ----
            float4 Pi4 = *reinterpret_cast<const float4*>(&Pis[tx*4]);
            float4 Ei4 = *reinterpret_cast<const float4*>(&Eis[tx*4]);
            float piv[4] = {Pi4.x, Pi4.y, Pi4.z, Pi4.w};
            float eiv[4] = {Ei4.x, Ei4.y, Ei4.z, Ei4.w};
            #pragma unroll
            for (int ti = 0; ti < 4; ti++) {
                int tl = ty*4 + ti;
                int t  = t0 + tl;
                float Pt = Pts[tl], Et = Ets[tl], iE = iEts[tl];
                float4 pv;
                float pout[4];
                #pragma unroll
                for (int ii = 0; ii < 4; ii++) {
                    int i = i0 + tx*4 + ii;
                    float p = 0.f;
                    if (i < t && t < Ss) {
                        float step = (float)(t - i);
                        float gd   = Pt - piv[ii];
                        float relv = (Et - eiv[ii]) * iE;
                        float pd   = step * gd * relv;
                        float decay = fexp2f(-th2 * pd);           // = exp(-theta*pd)
                        p = fexp2f((sm[ti][ii] * SCALE2) * decay); // = exp(raw*decay)
                    }
                    lsum[ti] += p;
                    pout[ii] = p;
                }
                pv.x = pout[0]; pv.y = pout[1]; pv.z = pout[2]; pv.w = pout[3];
                *reinterpret_cast<float4*>(&Ps[tl*PADP + tx*4]) = pv;
            }
            __syncthreads();

            // ---- GEMM2: ctx[t][d] += sum_i p[t][i] * V[i][d] ----
            #pragma unroll 4
            for (int i4 = 0; i4 < 16; i4++) {
                float v0 = Vs[(i4*4+0)*32 + lane];
                float v1 = Vs[(i4*4+1)*32 + lane];
                float v2 = Vs[(i4*4+2)*32 + lane];
                float v3 = Vs[(i4*4+3)*32 + lane];
                #pragma unroll
                for (int tt = 0; tt < 8; tt++) {
                    float4 p4 = *reinterpret_cast<const float4*>(&Ps[(w*8+tt)*PADP + i4*4]);
                    float a = acc[tt];
                    a = fmaf(p4.x, v0, a);
                    a = fmaf(p4.y, v1, a);
                    a = fmaf(p4.z, v2, a);
                    a = fmaf(p4.w, v3, a);
                    acc[tt] = a;
                }
            }
        }

        // reduce partial lsum across tx (within half-warp)
        #pragma unroll
        for (int off = 1; off < 16; off <<= 1) {
            #pragma unroll
            for (int ti = 0; ti < 4; ti++)
                lsum[ti] += __shfl_xor_sync(0xffffffffu, lsum[ti], off);
        }
        if (tx == 0) {
            #pragma unroll
            for (int ti = 0; ti < 4; ti++)
                Ls[ty*4 + ti] = lsum[ti];
        }
        __syncthreads();

        // write unnormalized partials (warp w owns t-rows w*8..w*8+7, lane = d)
        #pragma unroll
        for (int tt = 0; tt < 8; tt++) {
            int tl = w*8 + tt;
            int t  = t0 + tl;
            if (t < Ss) {
                g_pacc[r*(NROW*EMB) + (b*Ss + t)*128 + h*32 + lane] = acc[tt];
                if (lane == 0)
                    g_plsum[r*(NROW*Hh) + (b*Ss + t)*Hh + h] = Ls[tl];
            }
        }
        __syncthreads();   // before next phase restages
    }
}

// ---------------- kernel D: combine + final MLP (split-K) + sigmoid --------
// 8 rows/block, 256 threads: half = tid>>7 computes k in [half*128, half*128+128).
// 512 blocks -> ~3.5 blocks/SM, halved serial k-chain vs R12.
__global__ __launch_bounds__(256) void kD(
    const float* __restrict__ W1, const float* __restrict__ b1,
    const float* __restrict__ W2, const float* __restrict__ b2,
    float* __restrict__ out, int npred, int out_size)
{
    __shared__ __align__(16) float f_sh [8*256];   // feat rows (256 wide)
    __shared__ __align__(16) float ph_sh[8*128];   // half-1 partial
    __shared__ __align__(16) float h_sh [8*128];   // relu output
    __shared__ float w2s[128];

    int tid  = threadIdx.x;
    int c    = tid & 127;
    int half = tid >> 7;
    int row0 = blockIdx.x * 8;

    if (tid < 128) w2s[tid] = W2[tid];
    if (tid < 8) {
        int vrow = row0 + tid;
        if (vrow < Bb*Tt && Bb*Tt + vrow < out_size)
            out[Bb*Tt + vrow] = 1.0f;
    }

    // cooperative feat load: half 0 -> combined ctx cols, half 1 -> e cols
    #pragma unroll
    for (int r = 0; r < 8; r++) {
        int row = row0 + r;
        float v = 0.f;
        if (row < Bb*Tt) {
            int bb  = row / Tt;
            int t   = row - bb*Tt + 1;
            int base = (bb*Ss + t)*128 + c;
            if (half == 0) {
                int lidx = (bb*Ss + t)*Hh + (c >> 5);
                float a = g_pacc[base] + g_pacc[NROW*EMB + base] + g_pacc[2*(NROW*EMB) + base];
                float l = g_plsum[lidx] + g_plsum[NROW*Hh + lidx] + g_plsum[2*(NROW*Hh) + lidx];
                v = a / l;
            } else {
                v = g_e[base];
            }
        }
        f_sh[r*256 + half*128 + c] = v;
    }
    __syncthreads();

    // split-K GEMM: each half does 32 float4 k-steps
    float acc[8] = {0,0,0,0,0,0,0,0};
    {
        const float4* e4 = reinterpret_cast<const float4*>(f_sh);
        int kb = half * 32;                       // float4 offset within row
        #pragma unroll 4
        for (int k4 = 0; k4 < 32; k4++) {
            const float* wp = W1 + ((kb + k4)*4)*128 + c;
            float w0 = wp[0], w1 = wp[128], w2 = wp[256], w3 = wp[384];
            #pragma unroll
            for (int r = 0; r < 8; r++) {
                float4 ev = e4[r*64 + kb + k4];
                acc[r] = fmaf(ev.x, w0, acc[r]);
                acc[r] = fmaf(ev.y, w1, acc[r]);
                acc[r] = fmaf(ev.z, w2, acc[r]);
                acc[r] = fmaf(ev.w, w3, acc[r]);
            }
        }
    }
    if (half == 1) {
        #pragma unroll
        for (int r = 0; r < 8; r++) ph_sh[r*128 + c] = acc[r];
    }
    __syncthreads();
    if (half == 0) {
        float bb = b1[c];
        #pragma unroll
        for (int r = 0; r < 8; r++)
            h_sh[r*128 + c] = fmaxf(acc[r] + ph_sh[r*128 + c] + bb, 0.f);
    }
    __syncthreads();

    // logits: warp w handles row w (8 warps, 8 rows)
    int lane = tid & 31, w = tid >> 5;
    {
        int r = w;
        int row = row0 + r;
        if (row < npred) {
            float s = 0.f;
            #pragma unroll
            for (int cc = lane; cc < 128; cc += 32)
                s = fmaf(h_sh[r*128 + cc], w2s[cc], s);
            #pragma unroll
            for (int off = 16; off; off >>= 1)
                s += __shfl_xor_sync(0xffffffffu, s, off);
            if (lane == 0) {
                float logit = s + b2[0];
                out[row] = 1.0f / (1.0f + __expf(-logit));
            }
        }
    }
}

__global__ void kFill(float* out, int start, int n)
{
    int i = blockIdx.x*blockDim.x + threadIdx.x;
    if (i < n) out[start + i] = 1.0f;
}

// ---------------- launch ----------------
extern "C" void kernel_launch(void* const* d_in, const int* in_sizes, int n_in,
                              void* d_out, int out_size)
{
    const int*   idx      = (const int*)  d_in[0];
    const int*   flg      = (const int*)  d_in[1];
    const float* gaps     = (const float*)d_in[2];
    const float* item_emb = (const float*)d_in[3];
    const float* ans_emb  = (const float*)d_in[4];
    const float* Wq = (const float*)d_in[5];  const float* bq = (const float*)d_in[6];
    const float* Wk = (const float*)d_in[7];  const float* bk = (const float*)d_in[8];
    const float* Wv = (const float*)d_in[9];  const float* bv = (const float*)d_in[10];
    const float* Wh = (const float*)d_in[11]; const float* bh = (const float*)d_in[12];
    const float* W1 = (const float*)d_in[13]; const float* b1 = (const float*)d_in[14];
    const float* W2 = (const float*)d_in[15]; const float* b2 = (const float*)d_in[16];
    const float* th = (const float*)d_in[17];
    float* out = (float*)d_out;

    kA<<<NROW/16, 128>>>(idx, flg, item_emb, ans_emb, Wq, bq, Wk, bk, Wv, bv, Wh, bh);
    dim3 gB(5, Bb);
    kB<<<gB, 1024>>>(gaps, th);
    dim3 gC(8, NSPL, Bb*Hh);
    kC<<<gC, 256>>>();
    int npred = (out_size < Bb*Tt) ? out_size : Bb*Tt;
    kD<<<(Bb*Tt + 7)/8, 256>>>(W1, b1, W2, b2, out, npred, out_size);
    int extra = out_size - 2*Bb*Tt;
    if (extra > 0)
        kFill<<<(extra + 255)/256, 256>>>(out, 2*Bb*Tt, extra);
}